// round 16
// baseline (speedup 1.0000x reference)
#include <cuda_runtime.h>
#include <cuda_fp16.h>
#include <math_constants.h>
#include <cstdint>

// Problem constants
#define Bc 4
#define Nn 4096          // H*W
#define Cc 1024
#define BNN (4ull * 4096ull * 4096ull)

// ---------------- device scratch (no allocations allowed) ----------------
__device__ __half g_hi[(size_t)Bc * Nn * Cc];          // fp16 hi part of normalized emb
__device__ __half g_lo[(size_t)Bc * Nn * Cc];          // fp16 lo part (residual)
__device__ unsigned g_rowmax[Bc * Nn];                 // order-encoded max over non-ref cols
__device__ int   g_mask[Bc * Nn];                      // expanded 0/1 mask
__device__ int   g_refidx[Bc * 1024];                  // compacted ref-row indices per batch
__device__ int   g_k[Bc];                              // #ref per batch
__device__ float g_thresh[Bc];
__device__ int   g_mask_mode;                          // 0=u8, 1=i32, 2=f32

// order-preserving float <-> uint encode (for atomicMax on signed floats)
__device__ __forceinline__ unsigned ordenc(float f) {
    unsigned u = __float_as_uint(f);
    return (u & 0x80000000u) ? ~u : (u | 0x80000000u);
}
__device__ __forceinline__ float orddec(unsigned u) {
    return (u & 0x80000000u) ? __uint_as_float(u ^ 0x80000000u) : __uint_as_float(~u);
}
#define ORDENC_NEGINF 0x007FFFFFu   // ordenc(-inf)

__device__ __forceinline__ uint32_t smem_to_u32(const void* smem_ptr) {
    uint32_t addr;
    asm("{ .reg .u64 tmp; cvta.to.shared.u64 tmp, %1; cvt.u32.u64 %0, tmp; }"
        : "=r"(addr) : "l"(smem_ptr));
    return addr;
}

// ---------------- 1) classify mask dtype (also resets g_k each replay) --------
__global__ void classify_kernel(const unsigned* __restrict__ masks) {
    __shared__ int okI, okF;
    if (threadIdx.x == 0) {
        okI = 1; okF = 1;
        g_k[0] = 0; g_k[1] = 0; g_k[2] = 0; g_k[3] = 0;
    }
    __syncthreads();
    for (int i = threadIdx.x; i < 4096; i += blockDim.x) {
        unsigned w = masks[i];
        if (w != 0u && w != 1u)          okI = 0;
        if (w != 0u && w != 0x3F800000u) okF = 0;
    }
    __syncthreads();
    if (threadIdx.x == 0) g_mask_mode = okF ? 2 : (okI ? 1 : 0);
}

// ---------------- 2) expand mask + compact ref indices + init rowmax ----------------
__global__ void expand_kernel(const void* __restrict__ masks) {
    int idx = blockIdx.x * blockDim.x + threadIdx.x;
    if (idx >= Bc * Nn) return;
    int mode = g_mask_mode;
    int v;
    if (mode == 0)      v = (((const unsigned char*)masks)[idx] != 0);
    else if (mode == 1) v = (((const int*)masks)[idx] != 0);
    else                v = (((const float*)masks)[idx] != 0.0f);
    g_mask[idx] = v;
    g_rowmax[idx] = ORDENC_NEGINF;
    if (v) {
        int b = idx >> 12;
        int p = atomicAdd(&g_k[b], 1);
        if (p < 1024) g_refidx[b * 1024 + p] = idx & 4095;
    }
}

// ---------------- 3) normalize rows -> fp16 hi/lo split (warp per row) ----------------
__global__ void __launch_bounds__(256) normalize_kernel(const float* __restrict__ x) {
    const int lane = threadIdx.x & 31;
    const size_t row = (size_t)blockIdx.x * 8 + (threadIdx.x >> 5);
    const float4* xr = (const float4*)(x + row * (size_t)Cc);

    float4 v[8];
    float ss = 0.f;
    #pragma unroll
    for (int w = 0; w < 8; w++) {
        v[w] = xr[w * 32 + lane];
        ss += v[w].x * v[w].x + v[w].y * v[w].y + v[w].z * v[w].z + v[w].w * v[w].w;
    }
    #pragma unroll
    for (int o = 16; o > 0; o >>= 1) ss += __shfl_xor_sync(0xFFFFFFFFu, ss, o);
    const float inv = 1.0f / fmaxf(sqrtf(ss), 1e-12f);

    uint2* hp = (uint2*)(g_hi + row * (size_t)Cc);
    uint2* lp = (uint2*)(g_lo + row * (size_t)Cc);
    #pragma unroll
    for (int w = 0; w < 8; w++) {
        float y0 = v[w].x * inv, y1 = v[w].y * inv, y2 = v[w].z * inv, y3 = v[w].w * inv;
        __half h0 = __float2half_rn(y0), h1 = __float2half_rn(y1);
        __half h2 = __float2half_rn(y2), h3 = __float2half_rn(y3);
        float l0 = y0 - __half2float(h0), l1 = y1 - __half2float(h1);
        float l2 = y2 - __half2float(h2), l3 = y3 - __half2float(h3);
        union { __half2 b[2]; uint2 u; } H, L;
        H.b[0] = __half2(h0, h1); H.b[1] = __half2(h2, h3);
        L.b[0] = __half2(__float2half_rn(l0), __float2half_rn(l1));
        L.b[1] = __half2(__float2half_rn(l2), __float2half_rn(l3));
        hp[w * 32 + lane] = H.u;
        lp[w * 32 + lane] = L.u;
    }
}

// ---------------- 4) fp16 main GEMM: T = H*H^T (K=1024) ----------------
// CTA tile 128(M) x 64(N), BK=64 fp16 rows (=128B), 4 warps (4M x 1N), warp 32x64.
// Triangular coverage, 64-col strips: CTA (ti 0..31, tj 0..2ti+1); mirror tile
// transposed; diag tiles (tj>>1==ti) skip mirror AND all B loads (B aliases A).
// Direct tile + match zeros stored STRAIGHT FROM REGISTERS (no smem staging);
// smem transpose used only for the mirror on non-diag tiles.
// The hl+lh residual is ADDED exactly for ref rows by repair_kernel, which also
// owns rowmax -> thresh -> match bits.
#define BM 128
#define BNt 64
#define BK 64
#define NKCHUNK 16           // 1024/64
#define NTHREADS 128

#define SM_B0   32768
#define SM_TOTAL 49152       // A slots 0/16384, B slots 32768/40960

__device__ __forceinline__ void ldmx4(uint32_t* r, uint32_t addr) {
    asm volatile("ldmatrix.sync.aligned.m8n8.x4.shared.b16 {%0,%1,%2,%3}, [%4];"
                 : "=r"(r[0]), "=r"(r[1]), "=r"(r[2]), "=r"(r[3]) : "r"(addr));
}
__device__ __forceinline__ void mma16816(float* d, const uint32_t* a, const uint32_t* b) {
    asm volatile(
        "mma.sync.aligned.m16n8k16.row.col.f32.f16.f16.f32 "
        "{%0,%1,%2,%3}, {%4,%5,%6,%7}, {%8,%9}, {%0,%1,%2,%3};"
        : "+f"(d[0]), "+f"(d[1]), "+f"(d[2]), "+f"(d[3])
        : "r"(a[0]), "r"(a[1]), "r"(a[2]), "r"(a[3]), "r"(b[0]), "r"(b[1]));
}

__device__ __forceinline__ void stage_load(uint32_t smA, uint32_t smB,
        const __half* __restrict__ gA, const __half* __restrict__ gB,
        int rowBase, int colBase, int koff, int tid, bool skipB) {
    #pragma unroll
    for (int it = 0; it < 8; it++) {
        int i = tid + it * NTHREADS;
        int row = i >> 3, c = i & 7;
        uint32_t off = row * 128 + (((unsigned)(c ^ (row & 7))) << 4);
        const void* ga = gA + (((size_t)(rowBase + row)) << 10) + koff + c * 8;
        asm volatile("cp.async.cg.shared.global [%0], [%1], 16;" :: "r"(smA + off), "l"(ga));
    }
    if (!skipB) {
        #pragma unroll
        for (int it = 0; it < 4; it++) {
            int i = tid + it * NTHREADS;
            int row = i >> 3, c = i & 7;
            uint32_t off = row * 128 + (((unsigned)(c ^ (row & 7))) << 4);
            const void* gb = gB + (((size_t)(colBase + row)) << 10) + koff + c * 8;
            asm volatile("cp.async.cg.shared.global [%0], [%1], 16;" :: "r"(smB + off), "l"(gb));
        }
    }
}

__global__ void __launch_bounds__(NTHREADS, 4) gemm_kernel(float* __restrict__ simOut,
                                                           float* __restrict__ matchOut) {
    extern __shared__ char smem[];
    const uint32_t sb = smem_to_u32(smem);
    const int tid = threadIdx.x;
    const int lane = tid & 31, wid = tid >> 5;
    const int b = blockIdx.z;

    // decode t -> (ti, tj): t in [ti(ti+1), (ti+1)(ti+2)), tj = t - ti(ti+1)
    int t = blockIdx.x;
    int ti = (int)((sqrtf(4.0f * (float)t + 1.0f) - 1.0f) * 0.5f);
    while ((ti + 1) * (ti + 2) <= t) ti++;
    while (ti * (ti + 1) > t) ti--;
    int tj = t - ti * (ti + 1);              // 0 .. 2ti+1
    const int rowBase = ti * BM;             // 128-row band
    const int colBase = tj * BNt;            // 64-col strip
    const bool diag = ((tj >> 1) == ti);     // B rows subset of A rows

    const __half* gH = g_hi + (size_t)b * Nn * Cc;

    float acc[2][8][4];
    #pragma unroll
    for (int mt = 0; mt < 2; mt++)
        #pragma unroll
        for (int nt = 0; nt < 8; nt++)
            #pragma unroll
            for (int q = 0; q < 4; q++) acc[mt][nt][q] = 0.0f;

    const int wmBase = wid * 32;   // warp tile 32x64, 4 warps stacked in M

    // prefetch chunk 0; diag skips B (aliases inside A) for ALL chunks
    stage_load(sb, sb + SM_B0, gH, gH, rowBase, colBase, 0, tid, diag);
    asm volatile("cp.async.commit_group;");

    for (int kc = 0; kc < NKCHUNK; kc++) {
        asm volatile("cp.async.wait_group 0;");
        __syncthreads();
        if (kc + 1 < NKCHUNK) {
            int s = (kc + 1) & 1;
            stage_load(sb + s * 16384, sb + SM_B0 + s * 8192, gH, gH,
                       rowBase, colBase, (kc + 1) << 6, tid, diag);
            asm volatile("cp.async.commit_group;");
        }
        const uint32_t smA = sb + (kc & 1) * 16384;
        const uint32_t smB = diag ? (smA + (tj & 1) * 8192)
                                  : (sb + SM_B0 + (kc & 1) * 8192);

        #pragma unroll
        for (int ks = 0; ks < 4; ks++) {
            uint32_t afr[2][4];
            #pragma unroll
            for (int mt = 0; mt < 2; mt++) {
                int row = wmBase + mt * 16 + (lane & 7) + ((lane >> 3) & 1) * 8;
                int chunk = ks * 2 + (lane >> 4);
                ldmx4(afr[mt], smA + row * 128 + (((unsigned)(chunk ^ (row & 7))) << 4));
            }
            #pragma unroll
            for (int bt = 0; bt < 4; bt++) {
                int nrow = bt * 16 + (lane & 7) + (lane >> 4) * 8;
                int chunk = ks * 2 + ((lane >> 3) & 1);
                uint32_t r4[4];
                ldmx4(r4, smB + nrow * 128 + (((unsigned)(chunk ^ (nrow & 7))) << 4));
                uint32_t b0[2] = {r4[0], r4[1]};
                uint32_t b1[2] = {r4[2], r4[3]};
                #pragma unroll
                for (int mt = 0; mt < 2; mt++) {
                    mma16816(acc[mt][bt * 2],     afr[mt], b0);
                    mma16816(acc[mt][bt * 2 + 1], afr[mt], b1);
                }
            }
        }
    }

    float* simB = simOut + (size_t)b * Nn * Nn;
    float* matB = matchOut + (size_t)b * Nn * Nn;

    // ---------- direct tile: straight from registers, no smem ----------
    // thread owns rows wmBase+mt*16+(lane>>2)+{0,8}, cols 2*(lane&3)+nt*8+{0,1}
    {
        const int r0 = rowBase + wmBase + (lane >> 2);
        const int c0 = colBase + 2 * (lane & 3);
        #pragma unroll
        for (int mt = 0; mt < 2; mt++) {
            #pragma unroll
            for (int half = 0; half < 2; half++) {
                size_t rowOff = (size_t)(r0 + mt * 16 + half * 8) * Nn + c0;
                float* sp = simB + rowOff;
                float* mp = matB + rowOff;
                #pragma unroll
                for (int nt = 0; nt < 8; nt++) {
                    *(float2*)(sp + nt * 8) =
                        make_float2(acc[mt][nt][half * 2], acc[mt][nt][half * 2 + 1]);
                    *(float2*)(mp + nt * 8) = make_float2(0.f, 0.f);
                }
            }
        }
    }

    // ---------- mirror tile (non-diag): stage transpose through smem ----------
    if (!diag) {
        __syncthreads();   // all warps done with mainloop smem reads
        float* tile = (float*)smem;
        #pragma unroll
        for (int mt = 0; mt < 2; mt++) {
            #pragma unroll
            for (int nt = 0; nt < 8; nt++) {
                int r = wmBase + mt * 16 + (lane >> 2);
                int c = nt * 8 + 2 * (lane & 3);
                tile[r * 65 + c]       = acc[mt][nt][0];
                tile[r * 65 + c + 1]   = acc[mt][nt][1];
                tile[(r + 8) * 65 + c]     = acc[mt][nt][2];
                tile[(r + 8) * 65 + c + 1] = acc[mt][nt][3];
            }
        }
        __syncthreads();

        const float4 zero4 = make_float4(0.f, 0.f, 0.f, 0.f);
        #pragma unroll 4
        for (int it = 0; it < 16; it++) {
            int j = wid * 16 + it;
            float v0 = tile[(4 * lane + 0) * 65 + j];
            float v1 = tile[(4 * lane + 1) * 65 + j];
            float v2 = tile[(4 * lane + 2) * 65 + j];
            float v3 = tile[(4 * lane + 3) * 65 + j];
            size_t off = (size_t)(colBase + j) * Nn + rowBase + 4 * lane;
            *(float4*)(simB + off) = make_float4(v0, v1, v2, v3);
            *(float4*)(matB + off) = zero4;
        }
    }
}

// ---------------- 5) correction repair for ref rows: sim += lh + hl (K=2048) ----
// Reads the hh values the main GEMM wrote, adds the exact fp16 cross terms,
// writes back, and computes rowmax (atomicMax). Double-buffered cp.async.
// Region 0 (kc<16): A=lo, B=hi (lh). Region 1 (kc>=16): A=hi, B=lo (hl).
// Grid: (col-tile 0..31 of 128 cols, ref-group 0..31 of 32 rows, batch).
#define RNT 128
#define RNK 32               // 2048/64
// static smem: slot s at s*20480: A 4KB + B 16KB; cm at 40960; total 41472
__global__ void __launch_bounds__(RNT) repair_kernel(float* __restrict__ simOut) {
    __shared__ char rsm[41472];
    const uint32_t sb = smem_to_u32(rsm);
    const int tid = threadIdx.x, lane = tid & 31, wid = tid >> 5;
    const int ct = blockIdx.x;
    const int mg = blockIdx.y;
    const int b  = blockIdx.z;
    const int kk = g_k[b];
    if (mg * 32 >= kk) return;

    float* cm = (float*)(rsm + 40960);
    if (tid < 128)
        cm[tid] = g_mask[(b << 12) + ct * 128 + tid] ? -CUDART_INF_F : 0.0f;

    const int* refidx = g_refidx + b * 1024;
    int grow[2];
    #pragma unroll
    for (int it = 0; it < 2; it++) {
        int slot = mg * 32 + ((tid + it * RNT) >> 3);
        grow[it] = refidx[slot < kk ? slot : mg * 32];   // pad rows load dup data (unused)
    }

    const __half* gH = g_hi + (size_t)b * Nn * Cc;
    const __half* gL = g_lo + (size_t)b * Nn * Cc;

    float acc[2][4][4];
    #pragma unroll
    for (int mt = 0; mt < 2; mt++)
        #pragma unroll
        for (int nt = 0; nt < 4; nt++)
            #pragma unroll
            for (int q = 0; q < 4; q++) acc[mt][nt][q] = 0.0f;

    // chunk loader: slot base = s*20480 (A at +0, B at +4096)
    auto load_chunk = [&](int kc, int s) {
        int r = kc >> 4, ko = (kc & 15) << 6;
        const __half* sA = r ? gH : gL;   // region 0: lh (A=lo); region 1: hl (A=hi)
        const __half* sB = r ? gL : gH;
        uint32_t base = sb + s * 20480;
        #pragma unroll
        for (int it = 0; it < 2; it++) {
            int i = tid + it * RNT, row = i >> 3, c = i & 7;
            uint32_t off = row * 128 + (((unsigned)(c ^ (row & 7))) << 4);
            const void* ga = sA + (((size_t)grow[it]) << 10) + ko + c * 8;
            asm volatile("cp.async.cg.shared.global [%0], [%1], 16;" :: "r"(base + off), "l"(ga));
        }
        #pragma unroll
        for (int it = 0; it < 8; it++) {
            int i = tid + it * RNT, row = i >> 3, c = i & 7;
            uint32_t off = row * 128 + (((unsigned)(c ^ (row & 7))) << 4);
            const void* gb = sB + (((size_t)(ct * 128 + row)) << 10) + ko + c * 8;
            asm volatile("cp.async.cg.shared.global [%0], [%1], 16;" :: "r"(base + 4096 + off), "l"(gb));
        }
        asm volatile("cp.async.commit_group;");
    };

    load_chunk(0, 0);
    for (int kc = 0; kc < RNK; kc++) {
        if (kc + 1 < RNK) {
            load_chunk(kc + 1, (kc + 1) & 1);
            asm volatile("cp.async.wait_group 1;");
        } else {
            asm volatile("cp.async.wait_group 0;");
        }
        __syncthreads();
        const uint32_t base = sb + (kc & 1) * 20480;

        #pragma unroll
        for (int ks = 0; ks < 4; ks++) {
            uint32_t afr[2][4];
            #pragma unroll
            for (int mt = 0; mt < 2; mt++) {
                int row = mt * 16 + (lane & 7) + ((lane >> 3) & 1) * 8;
                int chunk = ks * 2 + (lane >> 4);
                ldmx4(afr[mt], base + row * 128 + (((unsigned)(chunk ^ (row & 7))) << 4));
            }
            #pragma unroll
            for (int bt = 0; bt < 2; bt++) {
                int nrow = wid * 32 + bt * 16 + (lane & 7) + (lane >> 4) * 8;
                int chunk = ks * 2 + ((lane >> 3) & 1);
                uint32_t r4[4];
                ldmx4(r4, base + 4096 + nrow * 128 + (((unsigned)(chunk ^ (nrow & 7))) << 4));
                uint32_t b0[2] = {r4[0], r4[1]};
                uint32_t b1[2] = {r4[2], r4[3]};
                #pragma unroll
                for (int mt = 0; mt < 2; mt++) {
                    mma16816(acc[mt][bt * 2],     afr[mt], b0);
                    mma16816(acc[mt][bt * 2 + 1], afr[mt], b1);
                }
            }
        }
        __syncthreads();   // all warps done with this slot before its next overwrite
    }

    // epilogue: f32 correction tile 32 x 132 overlaid on slot region
    float* tile = (float*)rsm;
    #pragma unroll
    for (int mt = 0; mt < 2; mt++) {
        #pragma unroll
        for (int nt = 0; nt < 4; nt++) {
            int r = mt * 16 + (lane >> 2);
            int c = wid * 32 + nt * 8 + 2 * (lane & 3);
            tile[r * 132 + c]       = acc[mt][nt][0];
            tile[r * 132 + c + 1]   = acc[mt][nt][1];
            tile[(r + 8) * 132 + c]     = acc[mt][nt][2];
            tile[(r + 8) * 132 + c + 1] = acc[mt][nt][3];
        }
    }
    __syncthreads();

    float* simB = simOut + (size_t)b * Nn * Nn;
    float cm0 = cm[4 * lane], cm1 = cm[4 * lane + 1], cm2 = cm[4 * lane + 2], cm3 = cm[4 * lane + 3];
    #pragma unroll
    for (int rr = 0; rr < 8; rr++) {
        int rloc = wid * 8 + rr;
        int slot = mg * 32 + rloc;
        if (slot >= kk) continue;            // pad rows: no RMW (uniform per warp)
        int gi = refidx[slot];
        float* sp = simB + (size_t)gi * Nn + ct * 128 + 4 * lane;
        float4 old = *(float4*)sp;
        const float* tr = tile + rloc * 132 + 4 * lane;
        float v0 = old.x + tr[0], v1 = old.y + tr[1];
        float v2 = old.z + tr[2], v3 = old.w + tr[3];
        *(float4*)sp = make_float4(v0, v1, v2, v3);
        float mx = fmaxf(fmaxf(v0 + cm0, v1 + cm1), fmaxf(v2 + cm2, v3 + cm3));
        #pragma unroll
        for (int o = 16; o > 0; o >>= 1) mx = fmaxf(mx, __shfl_xor_sync(0xFFFFFFFFu, mx, o));
        if (lane == 0)
            atomicMax(&g_rowmax[(b << 12) + gi], ordenc(mx));
    }
}

// ---------------- 6) per-batch lower median via compaction + rank-select ----------------
__global__ void __launch_bounds__(256) median_kernel(float* __restrict__ outThresh) {
    __shared__ float vals[4096];
    __shared__ int cnt;
    const int b = blockIdx.x;
    if (threadIdx.x == 0) cnt = 0;
    __syncthreads();
    for (int i = threadIdx.x; i < 4096; i += blockDim.x) {
        int idx = (b << 12) + i;
        if (g_mask[idx]) {
            int p = atomicAdd(&cnt, 1);
            vals[p] = orddec(g_rowmax[idx]);
        }
    }
    __syncthreads();
    const int k = cnt;
    const int med = (k - 1) >> 1;
    for (int c = threadIdx.x; c < k; c += blockDim.x) {
        float v = vals[c];
        int lt = 0, le = 0;
        for (int j = 0; j < k; j++) {
            float u = vals[j];
            lt += (u <  v);
            le += (u <= v);
        }
        if (lt <= med && med < le) {
            g_thresh[b] = v;
            outThresh[b] = v;
        }
    }
}

// ---------------- 7) match write — REF ROWS ONLY (zeros already laid by gemm) ----------------
__global__ void __launch_bounds__(128) match_kernel(const float* __restrict__ simIn,
                                                    float* __restrict__ matchOut) {
    const int bi = blockIdx.x;
    if (!g_mask[bi]) return;
    const int b = bi >> 12;

    const float th = g_thresh[b];
    const float4* src = (const float4*)(simIn + (size_t)bi * Nn);
    float4* dst = (float4*)(matchOut + (size_t)bi * Nn);
    const int* mj = &g_mask[b << 12];
    #pragma unroll
    for (int it = 0; it < 8; it++) {
        int q = threadIdx.x + it * 128;
        float4 s4 = src[q];
        const int* m4 = mj + 4 * q;
        float4 o;
        o.x = (!m4[0] && s4.x > th) ? 1.0f : 0.0f;
        o.y = (!m4[1] && s4.y > th) ? 1.0f : 0.0f;
        o.z = (!m4[2] && s4.z > th) ? 1.0f : 0.0f;
        o.w = (!m4[3] && s4.w > th) ? 1.0f : 0.0f;
        dst[q] = o;
    }
}

// ---------------- launch ----------------
extern "C" void kernel_launch(void* const* d_in, const int* in_sizes, int n_in,
                              void* d_out, int out_size) {
    const float* emb = (const float*)d_in[0];
    const void* masks = d_in[1];
    float* out = (float*)d_out;

    float* matchOut  = out;               // [B,N,N] as 0/1 floats
    float* simOut    = out + BNN;         // [B,N,N]
    float* threshOut = out + 2 * BNN;     // [B]

    cudaFuncSetAttribute(gemm_kernel, cudaFuncAttributeMaxDynamicSharedMemorySize, SM_TOTAL);

    classify_kernel<<<1, 256>>>((const unsigned*)masks);
    expand_kernel<<<(Bc * Nn + 255) / 256, 256>>>(masks);
    normalize_kernel<<<(Bc * Nn) / 8, 256>>>(emb);
    const int NPAIR = 32 * 33;                          // 1056 triangular 128x64 tiles
    gemm_kernel<<<dim3(NPAIR, 1, Bc), NTHREADS, SM_TOTAL>>>(simOut, matchOut);
    repair_kernel<<<dim3(32, 32, Bc), RNT>>>(simOut);
    median_kernel<<<Bc, 256>>>(threshOut);
    match_kernel<<<Bc * Nn, 128>>>(simOut, matchOut);
}

// round 17
// speedup vs baseline: 1.0839x; 1.0839x over previous
#include <cuda_runtime.h>
#include <cuda_fp16.h>
#include <math_constants.h>
#include <cstdint>

// Problem constants
#define Bc 4
#define Nn 4096          // H*W
#define Cc 1024
#define BNN (4ull * 4096ull * 4096ull)

// ---------------- device scratch (no allocations allowed) ----------------
__device__ __half g_hi[(size_t)Bc * Nn * Cc];          // fp16 hi part of normalized emb
__device__ __half g_lo[(size_t)Bc * Nn * Cc];          // fp16 lo part (residual)
__device__ unsigned g_rowmax[Bc * Nn];                 // order-encoded rowmax (approx then exact)
__device__ int   g_mask[Bc * Nn];                      // expanded 0/1 mask
__device__ int   g_refidx[Bc * 1024];                  // compacted ref-row indices per batch
__device__ int   g_k[Bc];                              // #ref per batch
__device__ float g_thresh[Bc];                         // exact threshold
__device__ float g_thresh_a[Bc];                       // approx threshold (phase A)
__device__ int   g_mask_mode;                          // 0=u8, 1=i32, 2=f32

// order-preserving float <-> uint encode (for atomicMax / storage of signed floats)
__device__ __forceinline__ unsigned ordenc(float f) {
    unsigned u = __float_as_uint(f);
    return (u & 0x80000000u) ? ~u : (u | 0x80000000u);
}
__device__ __forceinline__ float orddec(unsigned u) {
    return (u & 0x80000000u) ? __uint_as_float(u ^ 0x80000000u) : __uint_as_float(~u);
}
#define ORDENC_NEGINF 0x007FFFFFu   // ordenc(-inf)

__device__ __forceinline__ uint32_t smem_to_u32(const void* smem_ptr) {
    uint32_t addr;
    asm("{ .reg .u64 tmp; cvta.to.shared.u64 tmp, %1; cvt.u32.u64 %0, tmp; }"
        : "=r"(addr) : "l"(smem_ptr));
    return addr;
}

// ---------------- 1) classify mask dtype (also resets g_k each replay) --------
__global__ void classify_kernel(const unsigned* __restrict__ masks) {
    __shared__ int okI, okF;
    if (threadIdx.x == 0) {
        okI = 1; okF = 1;
        g_k[0] = 0; g_k[1] = 0; g_k[2] = 0; g_k[3] = 0;
    }
    __syncthreads();
    for (int i = threadIdx.x; i < 4096; i += blockDim.x) {
        unsigned w = masks[i];
        if (w != 0u && w != 1u)          okI = 0;
        if (w != 0u && w != 0x3F800000u) okF = 0;
    }
    __syncthreads();
    if (threadIdx.x == 0) g_mask_mode = okF ? 2 : (okI ? 1 : 0);
}

// ---------------- 2) expand mask + compact ref indices ----------------
__global__ void expand_kernel(const void* __restrict__ masks) {
    int idx = blockIdx.x * blockDim.x + threadIdx.x;
    if (idx >= Bc * Nn) return;
    int mode = g_mask_mode;
    int v;
    if (mode == 0)      v = (((const unsigned char*)masks)[idx] != 0);
    else if (mode == 1) v = (((const int*)masks)[idx] != 0);
    else                v = (((const float*)masks)[idx] != 0.0f);
    g_mask[idx] = v;
    g_rowmax[idx] = ORDENC_NEGINF;
    if (v) {
        int b = idx >> 12;
        int p = atomicAdd(&g_k[b], 1);
        if (p < 1024) g_refidx[b * 1024 + p] = idx & 4095;
    }
}

// ---------------- 3) normalize rows -> fp16 hi/lo split (warp per row) ----------------
__global__ void __launch_bounds__(256) normalize_kernel(const float* __restrict__ x) {
    const int lane = threadIdx.x & 31;
    const size_t row = (size_t)blockIdx.x * 8 + (threadIdx.x >> 5);
    const float4* xr = (const float4*)(x + row * (size_t)Cc);

    float4 v[8];
    float ss = 0.f;
    #pragma unroll
    for (int w = 0; w < 8; w++) {
        v[w] = xr[w * 32 + lane];
        ss += v[w].x * v[w].x + v[w].y * v[w].y + v[w].z * v[w].z + v[w].w * v[w].w;
    }
    #pragma unroll
    for (int o = 16; o > 0; o >>= 1) ss += __shfl_xor_sync(0xFFFFFFFFu, ss, o);
    const float inv = 1.0f / fmaxf(sqrtf(ss), 1e-12f);

    uint2* hp = (uint2*)(g_hi + row * (size_t)Cc);
    uint2* lp = (uint2*)(g_lo + row * (size_t)Cc);
    #pragma unroll
    for (int w = 0; w < 8; w++) {
        float y0 = v[w].x * inv, y1 = v[w].y * inv, y2 = v[w].z * inv, y3 = v[w].w * inv;
        __half h0 = __float2half_rn(y0), h1 = __float2half_rn(y1);
        __half h2 = __float2half_rn(y2), h3 = __float2half_rn(y3);
        float l0 = y0 - __half2float(h0), l1 = y1 - __half2float(h1);
        float l2 = y2 - __half2float(h2), l3 = y3 - __half2float(h3);
        union { __half2 b[2]; uint2 u; } H, L;
        H.b[0] = __half2(h0, h1); H.b[1] = __half2(h2, h3);
        L.b[0] = __half2(__float2half_rn(l0), __float2half_rn(l1));
        L.b[1] = __half2(__float2half_rn(l2), __float2half_rn(l3));
        hp[w * 32 + lane] = H.u;
        lp[w * 32 + lane] = L.u;
    }
}

// ---------------- 4) fp16 main GEMM: T = H*H^T (K=1024) — round-15 version ------
#define BM 128
#define BNt 64
#define BK 64
#define NKCHUNK 16           // 1024/64
#define NTHREADS 128

#define SM_B0   32768
#define SM_TOTAL 49152       // A slots 0/16384, B slots 32768/40960

__device__ __forceinline__ void ldmx4(uint32_t* r, uint32_t addr) {
    asm volatile("ldmatrix.sync.aligned.m8n8.x4.shared.b16 {%0,%1,%2,%3}, [%4];"
                 : "=r"(r[0]), "=r"(r[1]), "=r"(r[2]), "=r"(r[3]) : "r"(addr));
}
__device__ __forceinline__ void mma16816(float* d, const uint32_t* a, const uint32_t* b) {
    asm volatile(
        "mma.sync.aligned.m16n8k16.row.col.f32.f16.f16.f32 "
        "{%0,%1,%2,%3}, {%4,%5,%6,%7}, {%8,%9}, {%0,%1,%2,%3};"
        : "+f"(d[0]), "+f"(d[1]), "+f"(d[2]), "+f"(d[3])
        : "r"(a[0]), "r"(a[1]), "r"(a[2]), "r"(a[3]), "r"(b[0]), "r"(b[1]));
}

__device__ __forceinline__ void stage_load(uint32_t smA, uint32_t smB,
        const __half* __restrict__ gA, const __half* __restrict__ gB,
        int rowBase, int colBase, int koff, int tid, bool skipB) {
    #pragma unroll
    for (int it = 0; it < 8; it++) {
        int i = tid + it * NTHREADS;
        int row = i >> 3, c = i & 7;
        uint32_t off = row * 128 + (((unsigned)(c ^ (row & 7))) << 4);
        const void* ga = gA + (((size_t)(rowBase + row)) << 10) + koff + c * 8;
        asm volatile("cp.async.cg.shared.global [%0], [%1], 16;" :: "r"(smA + off), "l"(ga));
    }
    if (!skipB) {
        #pragma unroll
        for (int it = 0; it < 4; it++) {
            int i = tid + it * NTHREADS;
            int row = i >> 3, c = i & 7;
            uint32_t off = row * 128 + (((unsigned)(c ^ (row & 7))) << 4);
            const void* gb = gB + (((size_t)(colBase + row)) << 10) + koff + c * 8;
            asm volatile("cp.async.cg.shared.global [%0], [%1], 16;" :: "r"(smB + off), "l"(gb));
        }
    }
}

__global__ void __launch_bounds__(NTHREADS, 4) gemm_kernel(float* __restrict__ simOut,
                                                           float* __restrict__ matchOut) {
    extern __shared__ char smem[];
    const uint32_t sb = smem_to_u32(smem);
    const int tid = threadIdx.x;
    const int lane = tid & 31, wid = tid >> 5;
    const int b = blockIdx.z;

    int t = blockIdx.x;
    int ti = (int)((sqrtf(4.0f * (float)t + 1.0f) - 1.0f) * 0.5f);
    while ((ti + 1) * (ti + 2) <= t) ti++;
    while (ti * (ti + 1) > t) ti--;
    int tj = t - ti * (ti + 1);              // 0 .. 2ti+1
    const int rowBase = ti * BM;
    const int colBase = tj * BNt;
    const bool diag = ((tj >> 1) == ti);

    const __half* gH = g_hi + (size_t)b * Nn * Cc;

    float acc[2][8][4];
    #pragma unroll
    for (int mt = 0; mt < 2; mt++)
        #pragma unroll
        for (int nt = 0; nt < 8; nt++)
            #pragma unroll
            for (int q = 0; q < 4; q++) acc[mt][nt][q] = 0.0f;

    const int wmBase = wid * 32;

    stage_load(sb, sb + SM_B0, gH, gH, rowBase, colBase, 0, tid, diag);
    asm volatile("cp.async.commit_group;");

    for (int kc = 0; kc < NKCHUNK; kc++) {
        asm volatile("cp.async.wait_group 0;");
        __syncthreads();
        if (kc + 1 < NKCHUNK) {
            int s = (kc + 1) & 1;
            stage_load(sb + s * 16384, sb + SM_B0 + s * 8192, gH, gH,
                       rowBase, colBase, (kc + 1) << 6, tid, diag);
            asm volatile("cp.async.commit_group;");
        }
        const uint32_t smA = sb + (kc & 1) * 16384;
        const uint32_t smB = diag ? (smA + (tj & 1) * 8192)
                                  : (sb + SM_B0 + (kc & 1) * 8192);

        #pragma unroll
        for (int ks = 0; ks < 4; ks++) {
            uint32_t afr[2][4];
            #pragma unroll
            for (int mt = 0; mt < 2; mt++) {
                int row = wmBase + mt * 16 + (lane & 7) + ((lane >> 3) & 1) * 8;
                int chunk = ks * 2 + (lane >> 4);
                ldmx4(afr[mt], smA + row * 128 + (((unsigned)(chunk ^ (row & 7))) << 4));
            }
            #pragma unroll
            for (int bt = 0; bt < 4; bt++) {
                int nrow = bt * 16 + (lane & 7) + (lane >> 4) * 8;
                int chunk = ks * 2 + ((lane >> 3) & 1);
                uint32_t r4[4];
                ldmx4(r4, smB + nrow * 128 + (((unsigned)(chunk ^ (nrow & 7))) << 4));
                uint32_t b0[2] = {r4[0], r4[1]};
                uint32_t b1[2] = {r4[2], r4[3]};
                #pragma unroll
                for (int mt = 0; mt < 2; mt++) {
                    mma16816(acc[mt][bt * 2],     afr[mt], b0);
                    mma16816(acc[mt][bt * 2 + 1], afr[mt], b1);
                }
            }
        }
    }
    __syncthreads();

    // ---------- epilogue: stage f32 tile in smem (128 x 64, stride 65) ----------
    float* tile = (float*)smem;
    #pragma unroll
    for (int mt = 0; mt < 2; mt++) {
        #pragma unroll
        for (int nt = 0; nt < 8; nt++) {
            int r = wmBase + mt * 16 + (lane >> 2);
            int c = nt * 8 + 2 * (lane & 3);
            tile[r * 65 + c]       = acc[mt][nt][0];
            tile[r * 65 + c + 1]   = acc[mt][nt][1];
            tile[(r + 8) * 65 + c]     = acc[mt][nt][2];
            tile[(r + 8) * 65 + c + 1] = acc[mt][nt][3];
        }
    }
    __syncthreads();

    float* simB = simOut + (size_t)b * Nn * Nn;
    float* matB = matchOut + (size_t)b * Nn * Nn;
    const float4 zero4 = make_float4(0.f, 0.f, 0.f, 0.f);

    // direct tile: 128 rows x 64 cols; half-warp per row
    {
        const int fq = lane & 15;
        const int half = lane >> 4;
        #pragma unroll 4
        for (int it = 0; it < 16; it++) {
            int r = wid * 32 + it * 2 + half;
            const float* tr = tile + r * 65 + 4 * fq;
            size_t off = (size_t)(rowBase + r) * Nn + colBase + 4 * fq;
            *(float4*)(simB + off) = make_float4(tr[0], tr[1], tr[2], tr[3]);
            *(float4*)(matB + off) = zero4;
        }
    }
    // mirror tile: 64 rows x 128 cols (transpose); skipped on diag (duplicate)
    if (!diag) {
        #pragma unroll 4
        for (int it = 0; it < 16; it++) {
            int j = wid * 16 + it;
            float v0 = tile[(4 * lane + 0) * 65 + j];
            float v1 = tile[(4 * lane + 1) * 65 + j];
            float v2 = tile[(4 * lane + 2) * 65 + j];
            float v3 = tile[(4 * lane + 3) * 65 + j];
            size_t off = (size_t)(colBase + j) * Nn + rowBase + 4 * lane;
            *(float4*)(simB + off) = make_float4(v0, v1, v2, v3);
            *(float4*)(matB + off) = zero4;
        }
    }
}

// ---------------- 5a) approx rowmax over hh sim (ref rows only) ----------------
__global__ void __launch_bounds__(256) rowmax_approx_kernel(const float* __restrict__ simIn) {
    const int b = blockIdx.y;
    if ((int)blockIdx.x >= g_k[b]) return;
    const int gi = g_refidx[b * 1024 + blockIdx.x];
    const float* row = simIn + (size_t)b * Nn * Nn + (size_t)gi * Nn;
    const int* mj = &g_mask[b << 12];
    float mx = -CUDART_INF_F;
    for (int j = threadIdx.x; j < Nn; j += 256)
        if (!mj[j]) mx = fmaxf(mx, row[j]);
    #pragma unroll
    for (int o = 16; o > 0; o >>= 1) mx = fmaxf(mx, __shfl_xor_sync(0xFFFFFFFFu, mx, o));
    __shared__ float red[8];
    if ((threadIdx.x & 31) == 0) red[threadIdx.x >> 5] = mx;
    __syncthreads();
    if (threadIdx.x == 0) {
        float t = -CUDART_INF_F;
        #pragma unroll
        for (int w = 0; w < 8; w++) t = fmaxf(t, red[w]);
        g_rowmax[(b << 12) + gi] = ordenc(t);
    }
}

// ---------------- 5b) patch near-boundary entries exactly + exact rowmax -------
// Margins: measured hh-error sigma = 8e-6; 1.2e-4 = 15 sigma, 1.5e-4 = 18 sigma.
#define RM_MARG 1.2e-4f
#define TH_MARG 1.5e-4f
#define MAXCAND 128
__global__ void __launch_bounds__(256) patch_exact_kernel(float* __restrict__ simOut) {
    const int b = blockIdx.y;
    if ((int)blockIdx.x >= g_k[b]) return;
    const int gi = g_refidx[b * 1024 + blockIdx.x];
    float* row = simOut + (size_t)b * Nn * Nn + (size_t)gi * Nn;
    const int* mj = &g_mask[b << 12];
    const float tha = g_thresh_a[b];
    const float rma = orddec(g_rowmax[(b << 12) + gi]);

    __shared__ float xif[Cc];       // row vector reconstructed in fp32 (4KB)
    __shared__ int cands[MAXCAND];
    __shared__ int ncand;
    __shared__ float red[8];

    const __half* hi_i = g_hi + ((size_t)b * Nn + gi) * Cc;
    const __half* lo_i = g_lo + ((size_t)b * Nn + gi) * Cc;
    for (int k = threadIdx.x; k < Cc; k += 256)
        xif[k] = __half2float(hi_i[k]) + __half2float(lo_i[k]);
    if (threadIdx.x == 0) ncand = 0;
    __syncthreads();

    for (int j = threadIdx.x; j < Nn; j += 256) {
        if (!mj[j]) {
            float s = row[j];
            if (s >= rma - RM_MARG || fabsf(s - tha) <= TH_MARG) {
                int p = atomicAdd(&ncand, 1);
                if (p < MAXCAND) cands[p] = j;
            }
        }
    }
    __syncthreads();
    const int n = min(ncand, MAXCAND);

    __shared__ float vmax_s;
    if (threadIdx.x == 0) vmax_s = -CUDART_INF_F;
    for (int c = 0; c < n; c++) {
        int j = cands[c];
        const __half* hj = g_hi + ((size_t)b * Nn + j) * Cc;
        const __half* lj = g_lo + ((size_t)b * Nn + j) * Cc;
        float s = 0.f;
        for (int k = threadIdx.x; k < Cc; k += 256) {
            float xj = __half2float(hj[k]) + __half2float(lj[k]);
            s = fmaf(xif[k], xj, s);
        }
        #pragma unroll
        for (int o = 16; o > 0; o >>= 1) s += __shfl_xor_sync(0xFFFFFFFFu, s, o);
        if ((threadIdx.x & 31) == 0) red[threadIdx.x >> 5] = s;
        __syncthreads();
        if (threadIdx.x == 0) {
            float t = 0.f;
            #pragma unroll
            for (int w = 0; w < 8; w++) t += red[w];
            row[j] = t;                       // patch sim with exact value
            vmax_s = fmaxf(vmax_s, t);
        }
        __syncthreads();
    }
    if (threadIdx.x == 0)
        g_rowmax[(b << 12) + gi] = ordenc(vmax_s);   // exact rowmax (top candidate dominates)
}

// ---------------- 6) per-batch lower median via compaction + rank-select --------
// phase 0: writes g_thresh_a ; phase 1: writes g_thresh + output
__global__ void __launch_bounds__(256) median_kernel(float* __restrict__ outThresh, int phase) {
    __shared__ float vals[4096];
    __shared__ int cnt;
    const int b = blockIdx.x;
    if (threadIdx.x == 0) cnt = 0;
    __syncthreads();
    for (int i = threadIdx.x; i < 4096; i += blockDim.x) {
        int idx = (b << 12) + i;
        if (g_mask[idx]) {
            int p = atomicAdd(&cnt, 1);
            vals[p] = orddec(g_rowmax[idx]);
        }
    }
    __syncthreads();
    const int k = cnt;
    const int med = (k - 1) >> 1;
    for (int c = threadIdx.x; c < k; c += blockDim.x) {
        float v = vals[c];
        int lt = 0, le = 0;
        for (int j = 0; j < k; j++) {
            float u = vals[j];
            lt += (u <  v);
            le += (u <= v);
        }
        if (lt <= med && med < le) {
            if (phase == 0) {
                g_thresh_a[b] = v;
            } else {
                g_thresh[b] = v;
                outThresh[b] = v;
            }
        }
    }
}

// ---------------- 7) match write — REF ROWS ONLY (zeros already laid by gemm) ---
__global__ void __launch_bounds__(128) match_kernel(const float* __restrict__ simIn,
                                                    float* __restrict__ matchOut) {
    const int bi = blockIdx.x;
    if (!g_mask[bi]) return;
    const int b = bi >> 12;

    const float th = g_thresh[b];
    const float4* src = (const float4*)(simIn + (size_t)bi * Nn);
    float4* dst = (float4*)(matchOut + (size_t)bi * Nn);
    const int* mj = &g_mask[b << 12];
    #pragma unroll
    for (int it = 0; it < 8; it++) {
        int q = threadIdx.x + it * 128;
        float4 s4 = src[q];
        const int* m4 = mj + 4 * q;
        float4 o;
        o.x = (!m4[0] && s4.x > th) ? 1.0f : 0.0f;
        o.y = (!m4[1] && s4.y > th) ? 1.0f : 0.0f;
        o.z = (!m4[2] && s4.z > th) ? 1.0f : 0.0f;
        o.w = (!m4[3] && s4.w > th) ? 1.0f : 0.0f;
        dst[q] = o;
    }
}

// ---------------- launch ----------------
extern "C" void kernel_launch(void* const* d_in, const int* in_sizes, int n_in,
                              void* d_out, int out_size) {
    const float* emb = (const float*)d_in[0];
    const void* masks = d_in[1];
    float* out = (float*)d_out;

    float* matchOut  = out;               // [B,N,N] as 0/1 floats
    float* simOut    = out + BNN;         // [B,N,N]
    float* threshOut = out + 2 * BNN;     // [B]

    cudaFuncSetAttribute(gemm_kernel, cudaFuncAttributeMaxDynamicSharedMemorySize, SM_TOTAL);

    classify_kernel<<<1, 256>>>((const unsigned*)masks);
    expand_kernel<<<(Bc * Nn + 255) / 256, 256>>>(masks);
    normalize_kernel<<<(Bc * Nn) / 8, 256>>>(emb);
    const int NPAIR = 32 * 33;                          // 1056 triangular 128x64 tiles
    gemm_kernel<<<dim3(NPAIR, 1, Bc), NTHREADS, SM_TOTAL>>>(simOut, matchOut);
    rowmax_approx_kernel<<<dim3(1024, Bc), 256>>>(simOut);
    median_kernel<<<Bc, 256>>>(threshOut, 0);
    patch_exact_kernel<<<dim3(1024, Bc), 256>>>(simOut);
    median_kernel<<<Bc, 256>>>(threshOut, 1);
    match_kernel<<<Bc * Nn, 128>>>(simOut, matchOut);
}